// round 16
// baseline (speedup 1.0000x reference)
#include <cuda_runtime.h>
#include <cuda_fp16.h>
#include <math.h>

#define IMG   512
#define NB    16
#define OT    74
#define RGR   96
#define HALO  11
#define TPD   7
#define NTILES (NB*TPD*TPD)
#define ROWW  48          // half2 words per row (96 px)
#define RSTRW 52          // row stride in words (16B aligned, conflict-free)
#define MAPW  (RGR*RSTRW)
#define NTHR  576

#define P0 0
#define G0 MAPW
#define P1 (2*MAPW)
#define G1 (3*MAPW)
#define CBASE (4*MAPW)
#define CSZ  (OT*RSTRW)
#define REDW (CBASE + 2*CSZ)
#define TOTW (REDW + 104)
#define SMEM_BYTES (TOTW*4)   // 111072 B -> 2 CTAs/SM

#define FULLM 0xFFFFFFFFu
#define ONE2  0x3C003C00u
#define SHW(a,b) __byte_perm((a),(b),0x5432)

__device__ float g_part[NTILES*5];
__device__ unsigned g_count;

__device__ __forceinline__ unsigned hmax2u(unsigned a, unsigned b) {
    __half2 r = __hmax2(*(__half2*)&a, *(__half2*)&b); return *(unsigned*)&r; }
__device__ __forceinline__ unsigned hmin2u(unsigned a, unsigned b) {
    __half2 r = __hmin2(*(__half2*)&a, *(__half2*)&b); return *(unsigned*)&r; }
__device__ __forceinline__ unsigned max3w(unsigned a, unsigned b, unsigned c) {
    return hmax2u(a, hmax2u(b, c)); }
__device__ __forceinline__ unsigned or3w(unsigned a, unsigned b, unsigned c) {
    return a | b | c; }     // exact max for binary-half words -> single LOP3
__device__ __forceinline__ unsigned hadd2u(unsigned a, unsigned b) {
    __half2 r = __hadd2(*(__half2*)&a, *(__half2*)&b); return *(unsigned*)&r; }
__device__ __forceinline__ unsigned hsub2u(unsigned a, unsigned b) {
    __half2 r = __hsub2(*(__half2*)&a, *(__half2*)&b); return *(unsigned*)&r; }
__device__ __forceinline__ unsigned hfma2u(unsigned a, unsigned b, unsigned c) {
    __half2 r = __hfma2(*(__half2*)&a, *(__half2*)&b, *(__half2*)&c); return *(unsigned*)&r; }
// half-block named barrier (288 threads): id 1 = pred half, id 2 = gt half
__device__ __forceinline__ void barh(int id) {
    asm volatile("bar.sync %0, %1;" :: "r"(id), "r"(288) : "memory");
}

__global__ void __launch_bounds__(NTHR, 2)
k_main(const float* __restrict__ logits, const int* __restrict__ target,
       float* __restrict__ out) {
    extern __shared__ unsigned smu[];
    float* red = (float*)(smu + REDW);

    const int tid  = threadIdx.x;
    const int tile = blockIdx.x;
    const int b    = tile / (TPD*TPD);
    const int tr   = tile % (TPD*TPD);
    const int tyi  = tr / TPD, txi = tr % TPD;
    const int oy   = tyi*OT - HALO, ox = txi*OT - HALO;

    const float* lg = logits + (size_t)b*IMG*IMG;
    const int*   tg = target + (size_t)b*IMG*IMG;

    float a_bce = 0.f, a_p = 0.f, a_t = 0.f, a_pt = 0.f, a_hd = 0.f;

    // ---- load: replicate-clamped; P0 = pred (2 px/word), G0 = gt; owned-px partials
#pragma unroll
    for (int k = 0; k < 8; k++) {
        int idx = tid + k*NTHR;
        int r = idx / ROWW, w = idx - r*ROWW;
        int iy = oy + r, iyc = min(max(iy,0), IMG-1);
        int px0 = 2*w, ix0 = ox + px0, ix1 = ix0 + 1;
        int ixc0 = min(max(ix0,0), IMG-1), ixc1 = min(max(ix1,0), IMG-1);
        float x0 = lg[iyc*IMG+ixc0], x1 = lg[iyc*IMG+ixc1];
        float t0 = (float)tg[iyc*IMG+ixc0], t1 = (float)tg[iyc*IMG+ixc1];
        float p0 = 1.f/(1.f+expf(-x0)), p1 = 1.f/(1.f+expf(-x1));
        bool rown = (r >= HALO) & (r < HALO+OT) & (iy < IMG);
        if (rown & (px0 >= HALO) & (px0 < HALO+OT) & (ix0 < IMG)) {
            a_bce += fmaxf(x0,0.f) - x0*t0 + log1pf(expf(-fabsf(x0)));
            a_p += p0; a_t += t0; a_pt += p0*t0;
        }
        if (rown & (px0+1 >= HALO) & (px0+1 < HALO+OT) & (ix1 < IMG)) {
            a_bce += fmaxf(x1,0.f) - x1*t1 + log1pf(expf(-fabsf(x1)));
            a_p += p1; a_t += t1; a_pt += p1*t1;
        }
        __half2 hp = __floats2half2_rn(p0,p1), ht = __floats2half2_rn(t0,t1);
        smu[P0 + r*RSTRW + w] = *(unsigned*)&hp;
        smu[G0 + r*RSTRW + w] = *(unsigned*)&ht;
    }
    __syncthreads();

    // ---- thread mappings
    const int m  = tid / 288;            // 0=pred map, 1=gt map
    const int s  = tid % 288;
    const int rr = s % RGR, ch = s / RGR;   // hpass/boundary: row + 16-word chunk
    const int cg = s % 12,  rb = s / 12;    // vpass: uint4 col group + 4-row group
    const int vcol = cg*4, vr0 = rb*4;
    const int vm1 = rb ? vr0-1 : 0;
    const int vp4 = (rb == 23) ? RGR-1 : vr0+4;
    const int rm = rr ? rr-1 : 0, rp = (rr < RGR-1) ? rr+1 : RGR-1;
    unsigned* rawS = smu + (m ? G0 : P0);
    unsigned* bndD = smu + (m ? G1 : P1);
    unsigned* myC  = smu + CBASE + m*CSZ;
    unsigned* otC  = smu + CBASE + (1-m)*CSZ;
    const bool cenrow = (rr >= HALO) & (rr < HALO+OT);
    const int barid = 1 + m;

    // ---- boundary: maxpool3 - minpool3; centers stored as masked coefficients
    //      coef = (1 - 2*b) on OWNED pixels only, 0 elsewhere; constant part
    //      (sum of owned b) folded once with total weight 5.5 into a_hd.
    if (rr >= 1 && rr < RGR-1) {
        const bool rowin = ((unsigned)(oy+rr)) < (unsigned)IMG;
        const bool ownrow = cenrow && rowin;
        const bool colEdge = (txi == 0) | (txi == TPD-1);
        const int chiOwn = (txi == TPD-1) ? 79 : 85;   // owned px: [11, chiOwn)
        const int rs[3] = {rm, rr, rp};
        float cpart = 0.f;
#pragma unroll
        for (int sc = 0; sc < 2; sc++) {
            int wb = ch*16 + sc*8;
            unsigned vx[10], vn[10];
#pragma unroll
            for (int q = 0; q < 3; q++) {
                int bq = rs[q]*RSTRW + wb;
                uint4 A = *(const uint4*)(rawS+bq), Bv = *(const uint4*)(rawS+bq+4);
                unsigned em = wb ? rawS[bq-1] : A.x;
                unsigned ep = (wb+8 < ROWW) ? rawS[bq+8] : Bv.w;
                unsigned row[10] = {em,A.x,A.y,A.z,A.w,Bv.x,Bv.y,Bv.z,Bv.w,ep};
#pragma unroll
                for (int i = 0; i < 10; i++) {
                    if (q == 0) { vx[i] = row[i]; vn[i] = row[i]; }
                    else { vx[i] = hmax2u(vx[i],row[i]); vn[i] = hmin2u(vn[i],row[i]); }
                }
            }
            unsigned o[8], cf[8];
#pragma unroll
            for (int i = 0; i < 8; i++) {
                unsigned hx = max3w(vx[i+1], SHW(vx[i],vx[i+1]), SHW(vx[i+1],vx[i+2]));
                unsigned hn = hmin2u(vn[i+1], hmin2u(SHW(vn[i],vn[i+1]), SHW(vn[i+1],vn[i+2])));
                unsigned bnd = hsub2u(hx, hn);
                int p0 = ox + 2*(wb+i);
                if (colEdge) {
                    unsigned keep = (((unsigned)p0 < IMG) ? 0x0000FFFFu : 0u)
                                  | (((unsigned)(p0+1) < IMG) ? 0xFFFF0000u : 0u);
                    bnd &= keep;           // 0 is inert for max-dilation (bnd >= 0)
                }
                o[i] = rowin ? bnd : 0u;
                int q0 = 2*(wb+i);
                unsigned om = ((q0   >= HALO && q0   < chiOwn) ? 0x0000FFFFu : 0u)
                            | ((q0+1 >= HALO && q0+1 < chiOwn) ? 0xFFFF0000u : 0u);
                if (!ownrow) om = 0u;
                cf[i] = hsub2u(ONE2, hadd2u(o[i], o[i])) & om;   // (1-2b) masked
                unsigned bm = o[i] & om;                          // owned b values
                float2 fb = __half22float2(*(__half2*)&bm);
                cpart += fb.x + fb.y;
            }
            int base = rr*RSTRW + wb;
            *(uint4*)(bndD+base)   = make_uint4(o[0],o[1],o[2],o[3]);
            *(uint4*)(bndD+base+4) = make_uint4(o[4],o[5],o[6],o[7]);
            if (cenrow) {
                int cb = (rr-HALO)*RSTRW + wb;
                *(uint4*)(myC+cb)   = make_uint4(cf[0],cf[1],cf[2],cf[3]);
                *(uint4*)(myC+cb+4) = make_uint4(cf[4],cf[5],cf[6],cf[7]);
            }
        }
        a_hd += 5.5f * cpart;   // sum of weights 0.1*d, d=1..10
    }
    __syncthreads();   // full sync: coefficient centers cross halves here

    // ---- dilation cascade d = 1..10; halves independent -> named barriers;
    //      rows [1+d,95-d), vpass cols [d,96-d); gt pooling = OR (exact, LOP3);
    //      final iteration skips state stores (nothing reads them after).
    for (int d = 1; d <= 10; d++) {
        const int rlo = 1 + d, rhi = RGR - 1 - d;
        const bool vact = (vr0 + 4 > rlo) & (vr0 < rhi)
                        & (8*cg + 8 > d) & (8*cg < 96 - d);
        if (vact) {   // vertical max3: bndD -> rawS
            uint4 a  = *(const uint4*)(bndD + vm1*RSTRW + vcol);
            uint4 bb = *(const uint4*)(bndD + vr0*RSTRW + vcol);
            if (m == 0) {
#pragma unroll
                for (int j = 0; j < 4; j++) {
                    int rn = (j < 3) ? vr0+j+1 : vp4;
                    uint4 c = *(const uint4*)(bndD + rn*RSTRW + vcol);
                    uint4 o;
                    o.x = max3w(a.x,bb.x,c.x); o.y = max3w(a.y,bb.y,c.y);
                    o.z = max3w(a.z,bb.z,c.z); o.w = max3w(a.w,bb.w,c.w);
                    *(uint4*)(rawS + (vr0+j)*RSTRW + vcol) = o;
                    a = bb; bb = c;
                }
            } else {
#pragma unroll
                for (int j = 0; j < 4; j++) {
                    int rn = (j < 3) ? vr0+j+1 : vp4;
                    uint4 c = *(const uint4*)(bndD + rn*RSTRW + vcol);
                    uint4 o;
                    o.x = or3w(a.x,bb.x,c.x); o.y = or3w(a.y,bb.y,c.y);
                    o.z = or3w(a.z,bb.z,c.z); o.w = or3w(a.w,bb.w,c.w);
                    *(uint4*)(rawS + (vr0+j)*RSTRW + vcol) = o;
                    a = bb; bb = c;
                }
            }
        }
        barh(barid);
        if ((rr >= rlo) & (rr < rhi)) {        // horizontal max3 + FMA accumulation
            unsigned acc = 0u;
#pragma unroll
            for (int sc = 0; sc < 2; sc++) {
                int wb = ch*16 + sc*8, base = rr*RSTRW + wb;
                uint4 A = *(const uint4*)(rawS+base), Bv = *(const uint4*)(rawS+base+4);
                unsigned em = wb ? rawS[base-1] : A.x;
                unsigned ep = (wb+8 < ROWW) ? rawS[base+8] : Bv.w;
                unsigned w[10] = {em,A.x,A.y,A.z,A.w,Bv.x,Bv.y,Bv.z,Bv.w,ep};
                unsigned o[8];
                if (m == 0) {
#pragma unroll
                    for (int i = 0; i < 8; i++)
                        o[i] = max3w(w[i+1], SHW(w[i],w[i+1]), SHW(w[i+1],w[i+2]));
                } else {
#pragma unroll
                    for (int i = 0; i < 8; i++)
                        o[i] = or3w(w[i+1], SHW(w[i],w[i+1]), SHW(w[i+1],w[i+2]));
                }
                if (d < 10) {
                    *(uint4*)(bndD+base)   = make_uint4(o[0],o[1],o[2],o[3]);
                    *(uint4*)(bndD+base+4) = make_uint4(o[4],o[5],o[6],o[7]);
                }
                if (cenrow) {
                    int cb = (rr-HALO)*RSTRW + wb;
                    uint4 C1 = *(const uint4*)(otC+cb), C2 = *(const uint4*)(otC+cb+4);
                    unsigned cw[8] = {C1.x,C1.y,C1.z,C1.w,C2.x,C2.y,C2.z,C2.w};
#pragma unroll
                    for (int i = 0; i < 8; i++)
                        acc = hfma2u(o[i], cw[i], acc);
                }
            }
            if (cenrow) {
                float2 f = __half22float2(*(__half2*)&acc);
                a_hd += (0.1f*(float)d) * (f.x + f.y);
            }
        }
        barh(barid);
    }

    // ---- block reduction -> per-tile partials
    const unsigned FULL = 0xffffffffu;
#pragma unroll
    for (int o = 16; o; o >>= 1) {
        a_bce += __shfl_down_sync(FULL,a_bce,o); a_hd += __shfl_down_sync(FULL,a_hd,o);
        a_p += __shfl_down_sync(FULL,a_p,o); a_t += __shfl_down_sync(FULL,a_t,o);
        a_pt += __shfl_down_sync(FULL,a_pt,o);
    }
    int lane = tid & 31, w = tid >> 5;
    if (lane == 0) {
        red[w] = a_bce; red[18+w] = a_hd; red[36+w] = a_p;
        red[54+w] = a_t; red[72+w] = a_pt;
    }
    __syncthreads();
    if (tid == 0) {
        float sb=0, sh=0, sp=0, st=0, spt=0;
#pragma unroll
        for (int i = 0; i < 18; i++) {
            sb += red[i]; sh += red[18+i]; sp += red[36+i];
            st += red[54+i]; spt += red[72+i];
        }
        float* g = &g_part[tile*5];
        g[0]=sb; g[1]=sh; g[2]=sp; g[3]=st; g[4]=spt;
        __threadfence();
        unsigned v = atomicAdd(&g_count, 1u);
        red[96] = (v == NTILES-1) ? 1.f : 0.f;
    }
    __syncthreads();

    // ---- last CTA: final combine (single-launch pipeline)
    if (red[96] != 0.f) {
        __threadfence();
        __shared__ float simg[16][2], sbh[16][2];
        for (int img = w; img < 16; img += 18) {
            float bce=0, hd=0, p=0, t=0, pt=0;
            for (int i = lane; i < TPD*TPD; i += 32) {
                const float* g = &g_part[(img*TPD*TPD+i)*5];
                bce += g[0]; hd += g[1]; p += g[2]; t += g[3]; pt += g[4];
            }
#pragma unroll
            for (int o = 16; o; o >>= 1) {
                bce += __shfl_down_sync(FULL,bce,o); hd += __shfl_down_sync(FULL,hd,o);
                p += __shfl_down_sync(FULL,p,o); t += __shfl_down_sync(FULL,t,o);
                pt += __shfl_down_sync(FULL,pt,o);
            }
            if (lane == 0) {
                float dice = (2.f*pt + 1e-6f) / (p + t + 1e-6f + 1e-7f);
                float FP = p - pt, FN = t - pt;
                float tv = (pt + 1e-6f) / (pt + 0.7f*FP + 0.3f*FN + 1e-6f + 1e-7f);
                simg[img][0] = 1.f - dice;
                simg[img][1] = powf(fmaxf(1.f - tv, 0.f), 0.75f);
                sbh[img][0] = bce; sbh[img][1] = hd;
            }
        }
        __syncthreads();
        if (tid == 0) {
            float ds=0, fs=0, sb=0, sh=0;
#pragma unroll
            for (int i = 0; i < 16; i++) {
                ds += simg[i][0]; fs += simg[i][1];
                sb += sbh[i][0];  sh += sbh[i][1];
            }
            const float N = (float)NB*IMG*IMG;
            out[0] = sb/N + ds/16.f + fs/16.f + 0.1f*((sh/N)/(5.5f + 1e-8f));
            g_count = 0;
        }
    }
}

extern "C" void kernel_launch(void* const* d_in, const int* in_sizes, int n_in,
                              void* d_out, int out_size) {
    const float* logits = (const float*)d_in[0];
    const int*   target = (const int*)d_in[1];
    cudaFuncSetAttribute(k_main, cudaFuncAttributeMaxDynamicSharedMemorySize, SMEM_BYTES);
    k_main<<<NTILES, NTHR, SMEM_BYTES>>>(logits, target, (float*)d_out);
}

// round 17
// speedup vs baseline: 1.0768x; 1.0768x over previous
#include <cuda_runtime.h>
#include <cuda_fp16.h>
#include <math.h>

#define IMG   512
#define NB    16
#define OT    74
#define RGR   96
#define HALO  11
#define TPD   7
#define NTILES (NB*TPD*TPD)
#define ROWW  48          // half2 words per row (96 px)
#define RSTRW 52          // row stride in words (16B aligned, conflict-free)
#define MAPW  (RGR*RSTRW)
#define NTHR  576

#define P0 0
#define G0 MAPW
#define P1 (2*MAPW)
#define G1 (3*MAPW)
#define CBASE (4*MAPW)
#define CSZ  (OT*RSTRW)
#define REDW (CBASE + 2*CSZ)
#define TOTW (REDW + 104)
#define SMEM_BYTES (TOTW*4)   // 111072 B -> 2 CTAs/SM

#define FULLM 0xFFFFFFFFu
#define ONE2  0x3C003C00u
#define SHW(a,b) __byte_perm((a),(b),0x5432)

__device__ float g_part[NTILES*5];
__device__ unsigned g_count;

__device__ __forceinline__ unsigned hmax2u(unsigned a, unsigned b) {
    __half2 r = __hmax2(*(__half2*)&a, *(__half2*)&b); return *(unsigned*)&r; }
__device__ __forceinline__ unsigned hmin2u(unsigned a, unsigned b) {
    __half2 r = __hmin2(*(__half2*)&a, *(__half2*)&b); return *(unsigned*)&r; }
__device__ __forceinline__ unsigned max3w(unsigned a, unsigned b, unsigned c) {
    return hmax2u(a, hmax2u(b, c)); }
__device__ __forceinline__ unsigned hadd2u(unsigned a, unsigned b) {
    __half2 r = __hadd2(*(__half2*)&a, *(__half2*)&b); return *(unsigned*)&r; }
__device__ __forceinline__ unsigned hsub2u(unsigned a, unsigned b) {
    __half2 r = __hsub2(*(__half2*)&a, *(__half2*)&b); return *(unsigned*)&r; }
__device__ __forceinline__ unsigned hfma2u(unsigned a, unsigned b, unsigned c) {
    __half2 r = __hfma2(*(__half2*)&a, *(__half2*)&b, *(__half2*)&c); return *(unsigned*)&r; }
// half-block named barrier (288 threads): id 1 = pred half, id 2 = gt half
__device__ __forceinline__ void barh(int id) {
    asm volatile("bar.sync %0, %1;" :: "r"(id), "r"(288) : "memory");
}

__global__ void __launch_bounds__(NTHR, 2)
k_main(const float* __restrict__ logits, const int* __restrict__ target,
       float* __restrict__ out) {
    extern __shared__ unsigned smu[];
    float* red = (float*)(smu + REDW);

    const int tid  = threadIdx.x;
    const int tile = blockIdx.x;
    const int b    = tile / (TPD*TPD);
    const int tr   = tile % (TPD*TPD);
    const int tyi  = tr / TPD, txi = tr % TPD;
    const int oy   = tyi*OT - HALO, ox = txi*OT - HALO;

    const float* lg = logits + (size_t)b*IMG*IMG;
    const int*   tg = target + (size_t)b*IMG*IMG;

    float a_bce = 0.f, a_p = 0.f, a_t = 0.f, a_pt = 0.f, a_hd = 0.f;

    // ---- load: replicate-clamped; fast-math transcendental path (MUFU)
#pragma unroll
    for (int k = 0; k < 8; k++) {
        int idx = tid + k*NTHR;
        int r = idx / ROWW, w = idx - r*ROWW;
        int iy = oy + r, iyc = min(max(iy,0), IMG-1);
        int px0 = 2*w, ix0 = ox + px0, ix1 = ix0 + 1;
        int ixc0 = min(max(ix0,0), IMG-1), ixc1 = min(max(ix1,0), IMG-1);
        float x0 = lg[iyc*IMG+ixc0], x1 = lg[iyc*IMG+ixc1];
        float t0 = (float)tg[iyc*IMG+ixc0], t1 = (float)tg[iyc*IMG+ixc1];
        float p0 = __fdividef(1.f, 1.f + __expf(-x0));
        float p1 = __fdividef(1.f, 1.f + __expf(-x1));
        bool rown = (r >= HALO) & (r < HALO+OT) & (iy < IMG);
        if (rown & (px0 >= HALO) & (px0 < HALO+OT) & (ix0 < IMG)) {
            a_bce += fmaxf(x0,0.f) - x0*t0 + __logf(1.f + __expf(-fabsf(x0)));
            a_p += p0; a_t += t0; a_pt += p0*t0;
        }
        if (rown & (px0+1 >= HALO) & (px0+1 < HALO+OT) & (ix1 < IMG)) {
            a_bce += fmaxf(x1,0.f) - x1*t1 + __logf(1.f + __expf(-fabsf(x1)));
            a_p += p1; a_t += t1; a_pt += p1*t1;
        }
        __half2 hp = __floats2half2_rn(p0,p1), ht = __floats2half2_rn(t0,t1);
        smu[P0 + r*RSTRW + w] = *(unsigned*)&hp;
        smu[G0 + r*RSTRW + w] = *(unsigned*)&ht;
    }
    __syncthreads();

    // ---- thread mappings
    const int m  = tid / 288;            // 0=pred map, 1=gt map
    const int s  = tid % 288;
    const int rr = s % RGR, ch = s / RGR;   // hpass/boundary: row + 16-word chunk
    const int cg = s % 12,  rb = s / 12;    // vpass: uint4 col group + 4-row group
    const int vcol = cg*4, vr0 = rb*4;
    const int vm1 = rb ? vr0-1 : 0;
    const int vp4 = (rb == 23) ? RGR-1 : vr0+4;
    const int rm = rr ? rr-1 : 0, rp = (rr < RGR-1) ? rr+1 : RGR-1;
    unsigned* rawS = smu + (m ? G0 : P0);
    unsigned* bndD = smu + (m ? G1 : P1);
    unsigned* myC  = smu + CBASE + m*CSZ;
    unsigned* otC  = smu + CBASE + (1-m)*CSZ;
    const bool cenrow = (rr >= HALO) & (rr < HALO+OT);
    const int barid = 1 + m;

    // ---- boundary: maxpool3 - minpool3; centers stored as masked coefficients
    //      coef = (1 - 2*b) on OWNED pixels only, 0 elsewhere; constant part
    //      (sum of owned b) folded once with total weight 5.5 into a_hd.
    if (rr >= 1 && rr < RGR-1) {
        const bool rowin = ((unsigned)(oy+rr)) < (unsigned)IMG;
        const bool ownrow = cenrow && rowin;
        const bool colEdge = (txi == 0) | (txi == TPD-1);
        const int chiOwn = (txi == TPD-1) ? 79 : 85;   // owned px: [11, chiOwn)
        const int rs[3] = {rm, rr, rp};
        float cpart = 0.f;
#pragma unroll
        for (int sc = 0; sc < 2; sc++) {
            int wb = ch*16 + sc*8;
            unsigned vx[10], vn[10];
#pragma unroll
            for (int q = 0; q < 3; q++) {
                int bq = rs[q]*RSTRW + wb;
                uint4 A = *(const uint4*)(rawS+bq), Bv = *(const uint4*)(rawS+bq+4);
                unsigned em = wb ? rawS[bq-1] : A.x;
                unsigned ep = (wb+8 < ROWW) ? rawS[bq+8] : Bv.w;
                unsigned row[10] = {em,A.x,A.y,A.z,A.w,Bv.x,Bv.y,Bv.z,Bv.w,ep};
#pragma unroll
                for (int i = 0; i < 10; i++) {
                    if (q == 0) { vx[i] = row[i]; vn[i] = row[i]; }
                    else { vx[i] = hmax2u(vx[i],row[i]); vn[i] = hmin2u(vn[i],row[i]); }
                }
            }
            unsigned o[8], cf[8];
#pragma unroll
            for (int i = 0; i < 8; i++) {
                unsigned hx = max3w(vx[i+1], SHW(vx[i],vx[i+1]), SHW(vx[i+1],vx[i+2]));
                unsigned hn = hmin2u(vn[i+1], hmin2u(SHW(vn[i],vn[i+1]), SHW(vn[i+1],vn[i+2])));
                unsigned bnd = hsub2u(hx, hn);
                int p0 = ox + 2*(wb+i);
                if (colEdge) {
                    unsigned keep = (((unsigned)p0 < IMG) ? 0x0000FFFFu : 0u)
                                  | (((unsigned)(p0+1) < IMG) ? 0xFFFF0000u : 0u);
                    bnd &= keep;           // 0 is inert for max-dilation (bnd >= 0)
                }
                o[i] = rowin ? bnd : 0u;
                int q0 = 2*(wb+i);
                unsigned om = ((q0   >= HALO && q0   < chiOwn) ? 0x0000FFFFu : 0u)
                            | ((q0+1 >= HALO && q0+1 < chiOwn) ? 0xFFFF0000u : 0u);
                if (!ownrow) om = 0u;
                cf[i] = hsub2u(ONE2, hadd2u(o[i], o[i])) & om;   // (1-2b) masked
                unsigned bm = o[i] & om;                          // owned b values
                float2 fb = __half22float2(*(__half2*)&bm);
                cpart += fb.x + fb.y;
            }
            int base = rr*RSTRW + wb;
            *(uint4*)(bndD+base)   = make_uint4(o[0],o[1],o[2],o[3]);
            *(uint4*)(bndD+base+4) = make_uint4(o[4],o[5],o[6],o[7]);
            if (cenrow) {
                int cb = (rr-HALO)*RSTRW + wb;
                *(uint4*)(myC+cb)   = make_uint4(cf[0],cf[1],cf[2],cf[3]);
                *(uint4*)(myC+cb+4) = make_uint4(cf[4],cf[5],cf[6],cf[7]);
            }
        }
        a_hd += 5.5f * cpart;   // sum of weights 0.1*d, d=1..10
    }
    __syncthreads();   // full sync: coefficient centers cross halves here

    // ---- dilation cascade d = 1..10; halves independent -> named barriers;
    //      active rows [1+d, 95-d); accumulation = one HFMA2 per word;
    //      d=10 skips dead state stores (warp-uniform branch)
    for (int d = 1; d <= 10; d++) {
        const int rlo = 1 + d, rhi = RGR - 1 - d;
        if ((vr0 + 4 > rlo) & (vr0 < rhi)) {   // vertical max3: bndD -> rawS
            uint4 a  = *(const uint4*)(bndD + vm1*RSTRW + vcol);
            uint4 bb = *(const uint4*)(bndD + vr0*RSTRW + vcol);
#pragma unroll
            for (int j = 0; j < 4; j++) {
                int rn = (j < 3) ? vr0+j+1 : vp4;
                uint4 c = *(const uint4*)(bndD + rn*RSTRW + vcol);
                uint4 o;
                o.x = max3w(a.x,bb.x,c.x); o.y = max3w(a.y,bb.y,c.y);
                o.z = max3w(a.z,bb.z,c.z); o.w = max3w(a.w,bb.w,c.w);
                *(uint4*)(rawS + (vr0+j)*RSTRW + vcol) = o;
                a = bb; bb = c;
            }
        }
        barh(barid);
        if ((rr >= rlo) & (rr < rhi)) {        // horizontal max3 + FMA accumulation
            unsigned acc = 0u;
#pragma unroll
            for (int sc = 0; sc < 2; sc++) {
                int wb = ch*16 + sc*8, base = rr*RSTRW + wb;
                uint4 A = *(const uint4*)(rawS+base), Bv = *(const uint4*)(rawS+base+4);
                unsigned em = wb ? rawS[base-1] : A.x;
                unsigned ep = (wb+8 < ROWW) ? rawS[base+8] : Bv.w;
                unsigned w[10] = {em,A.x,A.y,A.z,A.w,Bv.x,Bv.y,Bv.z,Bv.w,ep};
                unsigned o[8];
#pragma unroll
                for (int i = 0; i < 8; i++)
                    o[i] = max3w(w[i+1], SHW(w[i],w[i+1]), SHW(w[i+1],w[i+2]));
                if (d < 10) {
                    *(uint4*)(bndD+base)   = make_uint4(o[0],o[1],o[2],o[3]);
                    *(uint4*)(bndD+base+4) = make_uint4(o[4],o[5],o[6],o[7]);
                }
                if (cenrow) {
                    int cb = (rr-HALO)*RSTRW + wb;
                    uint4 C1 = *(const uint4*)(otC+cb), C2 = *(const uint4*)(otC+cb+4);
                    unsigned cw[8] = {C1.x,C1.y,C1.z,C1.w,C2.x,C2.y,C2.z,C2.w};
#pragma unroll
                    for (int i = 0; i < 8; i++)
                        acc = hfma2u(o[i], cw[i], acc);
                }
            }
            if (cenrow) {
                float2 f = __half22float2(*(__half2*)&acc);
                a_hd += (0.1f*(float)d) * (f.x + f.y);
            }
        }
        barh(barid);
    }

    // ---- block reduction -> per-tile partials
    const unsigned FULL = 0xffffffffu;
#pragma unroll
    for (int o = 16; o; o >>= 1) {
        a_bce += __shfl_down_sync(FULL,a_bce,o); a_hd += __shfl_down_sync(FULL,a_hd,o);
        a_p += __shfl_down_sync(FULL,a_p,o); a_t += __shfl_down_sync(FULL,a_t,o);
        a_pt += __shfl_down_sync(FULL,a_pt,o);
    }
    int lane = tid & 31, w = tid >> 5;
    if (lane == 0) {
        red[w] = a_bce; red[18+w] = a_hd; red[36+w] = a_p;
        red[54+w] = a_t; red[72+w] = a_pt;
    }
    __syncthreads();
    if (tid == 0) {
        float sb=0, sh=0, sp=0, st=0, spt=0;
#pragma unroll
        for (int i = 0; i < 18; i++) {
            sb += red[i]; sh += red[18+i]; sp += red[36+i];
            st += red[54+i]; spt += red[72+i];
        }
        float* g = &g_part[tile*5];
        g[0]=sb; g[1]=sh; g[2]=sp; g[3]=st; g[4]=spt;
        __threadfence();
        unsigned v = atomicAdd(&g_count, 1u);
        red[96] = (v == NTILES-1) ? 1.f : 0.f;
    }
    __syncthreads();

    // ---- last CTA: final combine (single-launch pipeline)
    if (red[96] != 0.f) {
        __threadfence();
        __shared__ float simg[16][2], sbh[16][2];
        for (int img = w; img < 16; img += 18) {
            float bce=0, hd=0, p=0, t=0, pt=0;
            for (int i = lane; i < TPD*TPD; i += 32) {
                const float* g = &g_part[(img*TPD*TPD+i)*5];
                bce += g[0]; hd += g[1]; p += g[2]; t += g[3]; pt += g[4];
            }
#pragma unroll
            for (int o = 16; o; o >>= 1) {
                bce += __shfl_down_sync(FULL,bce,o); hd += __shfl_down_sync(FULL,hd,o);
                p += __shfl_down_sync(FULL,p,o); t += __shfl_down_sync(FULL,t,o);
                pt += __shfl_down_sync(FULL,pt,o);
            }
            if (lane == 0) {
                float dice = (2.f*pt + 1e-6f) / (p + t + 1e-6f + 1e-7f);
                float FP = p - pt, FN = t - pt;
                float tv = (pt + 1e-6f) / (pt + 0.7f*FP + 0.3f*FN + 1e-6f + 1e-7f);
                simg[img][0] = 1.f - dice;
                simg[img][1] = powf(fmaxf(1.f - tv, 0.f), 0.75f);
                sbh[img][0] = bce; sbh[img][1] = hd;
            }
        }
        __syncthreads();
        if (tid == 0) {
            float ds=0, fs=0, sb=0, sh=0;
#pragma unroll
            for (int i = 0; i < 16; i++) {
                ds += simg[i][0]; fs += simg[i][1];
                sb += sbh[i][0];  sh += sbh[i][1];
            }
            const float N = (float)NB*IMG*IMG;
            out[0] = sb/N + ds/16.f + fs/16.f + 0.1f*((sh/N)/(5.5f + 1e-8f));
            g_count = 0;
        }
    }
}

extern "C" void kernel_launch(void* const* d_in, const int* in_sizes, int n_in,
                              void* d_out, int out_size) {
    const float* logits = (const float*)d_in[0];
    const int*   target = (const int*)d_in[1];
    cudaFuncSetAttribute(k_main, cudaFuncAttributeMaxDynamicSharedMemorySize, SMEM_BYTES);
    k_main<<<NTILES, NTHR, SMEM_BYTES>>>(logits, target, (float*)d_out);
}